// round 8
// baseline (speedup 1.0000x reference)
#include <cuda_runtime.h>
#include <cfloat>

#define BATCH 8
#define NPT   1024
#define KNN   20
#define EPSV  1e-6f
#define CTOT  169   // 21+21+42+85 concat channels
#define MAXCOUT 85
#define TOTPT (BATCH * NPT)
#define HALFPT (TOTPT / 2)

typedef unsigned long long u64;

// ---- packed f32x2 helpers (sm_10x FFMA2) ----
__device__ __forceinline__ u64 pk2(float lo, float hi) {
    u64 r; asm("mov.b64 %0,{%1,%2};" : "=l"(r) : "f"(lo), "f"(hi)); return r;
}
__device__ __forceinline__ void fma2(u64& d, u64 a, u64 b) {
    asm("fma.rn.f32x2 %0,%1,%2,%0;" : "+l"(d) : "l"(a), "l"(b));
}
__device__ __forceinline__ float2 up2(u64 v) {
    float2 r; asm("mov.b64 {%0,%1},%2;" : "=f"(r.x), "=f"(r.y) : "l"(v)); return r;
}
// monotone float -> uint (order-preserving)
__device__ __forceinline__ unsigned ford(float v) {
    unsigned u = __float_as_uint(v);
    return (u & 0x80000000u) ? ~u : (u | 0x80000000u);
}

// -------- scratch (no allocations allowed) --------
__device__ float  g_feat[BATCH * CTOT * 3 * NPT];        // [B][169][3][N]
__device__ int    g_idx[BATCH * NPT * KNN];
__device__ float2 g_y  [BATCH * NPT * MAXCOUT * 3];      // [pt][o][f] {yf,yd}
__device__ float2 g_cmb[BATCH * NPT * MAXCOUT * 3];      // [pt][o][f] {pc-yf, dc-yd}

// ================= knn (fused xx) + warp-parallel top-k =================
// key_j = 2*dot(xi,xj) - xx_j  (row-constant xx_i dropped; ranking unchanged)
// TI=16 rows/block; 512 threads; j-tile=2; one row per warp for top-k.
template <int D>
__global__ __launch_bounds__(512, 2)
void knn_kernel(const float* __restrict__ cur, int Ctot, int coff, int blkoff)
{
    const int TI = 16;
    extern __shared__ float smraw[];
    float (*sdist)[NPT] = (float(*)[NPT])smraw;          // [TI][NPT]
    u64   (*sxp)[8]     = (u64(*)[8])(smraw + TI * NPT); // [D][8] query rowpairs

    int blk = blockIdx.x + blkoff;
    int b  = blk / (NPT / TI);
    int i0 = (blk % (NPT / TI)) * TI;
    int tid = threadIdx.x;
    const float* base = cur + (size_t)(b * Ctot + coff) * 3 * NPT;

    for (int f = tid; f < D; f += 512) {
        #pragma unroll
        for (int rp = 0; rp < 8; rp++) {
            float qa = base[f * NPT + i0 + 2 * rp];
            float qb = base[f * NPT + i0 + 2 * rp + 1];
            sxp[f][rp] = pk2(qa, qb);
        }
    }
    __syncthreads();

    // ---- distance phase: thread handles 2 contiguous j for all 16 rows ----
    {
        int j0 = tid * 2;
        u64 acc[8][2];
        float xx0 = 0.f, xx1 = 0.f;
        #pragma unroll
        for (int rp = 0; rp < 8; rp++) { acc[rp][0] = 0ull; acc[rp][1] = 0ull; }

        #pragma unroll 2
        for (int f = 0; f < D; f++) {
            float2 xv = *(const float2*)(base + f * NPT + j0);
            u64 xp0 = pk2(xv.x, xv.x), xp1 = pk2(xv.y, xv.y);
            #pragma unroll
            for (int rp = 0; rp < 8; rp++) {
                u64 q = sxp[f][rp];
                fma2(acc[rp][0], q, xp0);
                fma2(acc[rp][1], q, xp1);
            }
            xx0 = fmaf(xv.x, xv.x, xx0);
            xx1 = fmaf(xv.y, xv.y, xx1);
        }
        #pragma unroll
        for (int rp = 0; rp < 8; rp++) {
            float2 v0 = up2(acc[rp][0]), v1 = up2(acc[rp][1]);
            float2 lo = make_float2(2.f * v0.x - xx0, 2.f * v1.x - xx1);
            float2 hi = make_float2(2.f * v0.y - xx0, 2.f * v1.y - xx1);
            *(float2*)&sdist[2 * rp][j0]     = lo;
            *(float2*)&sdist[2 * rp + 1][j0] = hi;
        }
    }
    __syncthreads();

    // ---- top-k: warp w handles row w. Lane caches argmax of strip {lane+32t}.
    //      Zeroed winner element is only ever re-read by lane (wbi>>5), which
    //      performs the write itself (same-lane RAW is program-ordered). ----
    int w = tid >> 5, lane = tid & 31;
    float* row = sdist[w];
    int ob = (b * NPT + i0 + w) * KNN;

    unsigned ck; int ci;
    {
        float lb = -FLT_MAX; int li = 0x7fffffff;
        #pragma unroll 8
        for (int t = 0; t < 32; t++) {
            float v = row[lane + 32 * t];
            if (v > lb) { lb = v; li = lane + 32 * t; }   // ascending t => min idx on ties
        }
        ck = ford(lb); ci = li;
    }
    for (int it = 0; it < KNN; it++) {
        unsigned mx = __reduce_max_sync(0xffffffffu, ck);
        int wb = __reduce_min_sync(0xffffffffu, (ck == mx) ? ci : 0x7fffffff);
        if (lane == 0) g_idx[ob + it] = wb;
        int own = wb & 31;
        if (lane == (wb >> 5)) row[wb] = -FLT_MAX;
        float v = row[own + 32 * lane];
        unsigned k2 = ford(v);
        unsigned m2 = __reduce_max_sync(0xffffffffu, k2);
        int i2 = __reduce_min_sync(0xffffffffu, (k2 == m2) ? (own + 32 * lane) : 0x7fffffff);
        if (lane == own) { ck = m2; ci = i2; }
    }
}

// ================= per-point linear maps =================
template <int CIN, int COUT>
__global__ void ymap_kernel(const float* __restrict__ cur, int Ctot, int coff,
                            const float* __restrict__ Wf, const float* __restrict__ Wd)
{
    const int IN2 = 2 * CIN;
    extern __shared__ float sm[];
    float4* sW = (float4*)sm;                 // [CIN][COUT] {wfL,wdL,wfR,wdR}
    float*  sx = sm + 4 * CIN * COUT;         // [3*CIN][32]

    int tid = threadIdx.x;
    int nn = tid & 31, og = tid >> 5;
    int pt0 = blockIdx.x * 32;
    int b = pt0 >> 10, n0 = pt0 & (NPT - 1);
    const float* base = cur + (size_t)(b * Ctot + coff) * 3 * NPT;

    for (int t = tid; t < CIN * COUT; t += blockDim.x) {
        int c = t / COUT, o = t - c * COUT;
        sW[t] = make_float4(Wf[o * IN2 + c], Wd[o * IN2 + c],
                            Wf[o * IN2 + CIN + c], Wd[o * IN2 + CIN + c]);
    }
    for (int t = tid; t < 3 * CIN * 32; t += blockDim.x) {
        int row = t >> 5, col = t & 31;
        sx[t] = base[row * NPT + n0 + col];
    }
    __syncthreads();

    int pt = pt0 + nn;
    for (int o = og; o < COUT; o += 8) {
        u64 accL0 = 0ull, accL1 = 0ull, accL2 = 0ull;
        u64 accR0 = 0ull, accR1 = 0ull, accR2 = 0ull;
        for (int c = 0; c < CIN; c++) {
            float4 w = sW[c * COUT + o];
            u64 wl = pk2(w.x, w.y);
            u64 wr = pk2(w.z, w.w);
            float x0 = sx[(c * 3 + 0) * 32 + nn];
            float x1 = sx[(c * 3 + 1) * 32 + nn];
            float x2 = sx[(c * 3 + 2) * 32 + nn];
            u64 p0 = pk2(x0, x0), p1 = pk2(x1, x1), p2 = pk2(x2, x2);
            fma2(accL0, wl, p0); fma2(accR0, wr, p0);
            fma2(accL1, wl, p1); fma2(accR1, wr, p1);
            fma2(accL2, wl, p2); fma2(accR2, wr, p2);
        }
        float2* yo = g_y   + ((size_t)pt * COUT + o) * 3;
        float2* co = g_cmb + ((size_t)pt * COUT + o) * 3;
        float2 l0 = up2(accL0), l1 = up2(accL1), l2 = up2(accL2);
        float2 r0 = up2(accR0), r1 = up2(accR1), r2 = up2(accR2);
        yo[0] = l0; yo[1] = l1; yo[2] = l2;
        co[0] = make_float2(r0.x - l0.x, r0.y - l0.y);
        co[1] = make_float2(r1.x - l1.x, r1.y - l1.y);
        co[2] = make_float2(r2.x - l2.x, r2.y - l2.y);
    }
}

// ================= gather + leaky combine + mean over k =================
// blockDim = COUT*P exactly; P divides HALFPT.
template <int COUT, int P>
__global__ void pair_kernel(int ooff, int ptbase)
{
    const int TPB = COUT * P;
    __shared__ int sidx[P][KNN];
    int tid = threadIdx.x;
    int pt0 = ptbase + blockIdx.x * P;

    for (int t = tid; t < P * KNN; t += TPB)
        sidx[t / KNN][t % KNN] = g_idx[pt0 * KNN + t];
    __syncthreads();

    int ln = tid / COUT, o = tid - ln * COUT;
    int pt = pt0 + ln;
    int b = pt >> 10, n = pt & (NPT - 1);

    const float2* cmb = g_cmb + ((size_t)pt * COUT + o) * 3;
    float2 c0 = cmb[0], c1 = cmb[1], c2 = cmb[2];

    float a0 = 0.f, a1 = 0.f, a2 = 0.f;
    #pragma unroll 5
    for (int j = 0; j < KNN; j++) {
        int nj = sidx[ln][j];
        const float2* y = g_y + (((size_t)(b << 10) + nj) * COUT + o) * 3;
        float2 y0 = y[0], y1 = y[1], y2 = y[2];
        float P0 = y0.x + c0.x, D0 = y0.y + c0.y;
        float P1 = y1.x + c1.x, D1 = y1.y + c1.y;
        float P2 = y2.x + c2.x, D2 = y2.y + c2.y;
        float dot = P0 * D0 + P1 * D1 + P2 * D2;
        float dsq = D0 * D0 + D1 * D1 + D2 * D2;
        float s = dot / (dsq + EPSV);
        float s0, s1, s2;
        if (dot >= 0.f) { s0 = P0; s1 = P1; s2 = P2; }
        else { s0 = P0 - s * D0; s1 = P1 - s * D1; s2 = P2 - s * D2; }
        a0 += 0.2f * P0 + 0.8f * s0;
        a1 += 0.2f * P1 + 0.8f * s1;
        a2 += 0.2f * P2 + 0.8f * s2;
    }
    const float invK = 1.f / KNN;
    float* fo = g_feat + (((size_t)b * CTOT + ooff + o) * 3) * NPT + n;
    fo[0 * NPT] = a0 * invK;
    fo[1 * NPT] = a1 * invK;
    fo[2 * NPT] = a2 * invK;
}

// ========== final VN layer + mean over N (n-pair f32x2 packed) ==========
__global__ void final_kernel(const float* __restrict__ Wf, const float* __restrict__ Wd,
                             float* __restrict__ out)
{
    const int OT = 11;               // 341 = 31 * 11
    const int CI = CTOT;
    __shared__ u64   sWfp[OT * CI];  // {w,w}
    __shared__ u64   sWdp[CI];
    __shared__ float sacc[OT * 3];
    int b  = blockIdx.x / 31;
    int o0 = (blockIdx.x % 31) * OT;
    int tid = threadIdx.x;

    for (int t = tid; t < OT * CI; t += 256) {
        int o = t / CI, c = t - o * CI;
        float w = Wf[(o0 + o) * CI + c];
        sWfp[t] = pk2(w, w);
    }
    for (int t = tid; t < CI; t += 256) { float w = Wd[t]; sWdp[t] = pk2(w, w); }
    if (tid < OT * 3) sacc[tid] = 0.f;
    __syncthreads();

    float sum[OT][3];
    #pragma unroll
    for (int o = 0; o < OT; o++) { sum[o][0] = sum[o][1] = sum[o][2] = 0.f; }

    const float* fb = g_feat + (size_t)b * CTOT * 3 * NPT;
    for (int it = 0; it < 2; it++) {
        int n = 2 * (tid + it * 256);          // even, n and n+1 packed
        u64 p0[OT], p1[OT], p2[OT];
        u64 d0 = 0ull, d1 = 0ull, d2 = 0ull;
        #pragma unroll
        for (int o = 0; o < OT; o++) { p0[o] = p1[o] = p2[o] = 0ull; }

        for (int c = 0; c < CI; c++) {
            u64 x0 = *(const u64*)(fb + (c * 3 + 0) * NPT + n);
            u64 x1 = *(const u64*)(fb + (c * 3 + 1) * NPT + n);
            u64 x2 = *(const u64*)(fb + (c * 3 + 2) * NPT + n);
            u64 wd = sWdp[c];
            fma2(d0, wd, x0); fma2(d1, wd, x1); fma2(d2, wd, x2);
            #pragma unroll
            for (int o = 0; o < OT; o++) {
                u64 wf = sWfp[o * CI + c];
                fma2(p0[o], wf, x0); fma2(p1[o], wf, x1); fma2(p2[o], wf, x2);
            }
        }
        float2 D0 = up2(d0), D1 = up2(d1), D2 = up2(d2);
        float invA = 1.f / (D0.x * D0.x + D1.x * D1.x + D2.x * D2.x + EPSV);
        float invB = 1.f / (D0.y * D0.y + D1.y * D1.y + D2.y * D2.y + EPSV);
        #pragma unroll
        for (int o = 0; o < OT; o++) {
            float2 P0 = up2(p0[o]), P1 = up2(p1[o]), P2 = up2(p2[o]);
            {
                float dot = P0.x * D0.x + P1.x * D1.x + P2.x * D2.x;
                float s0, s1, s2;
                if (dot >= 0.f) { s0 = P0.x; s1 = P1.x; s2 = P2.x; }
                else {
                    float sc = dot * invA;
                    s0 = P0.x - sc * D0.x; s1 = P1.x - sc * D1.x; s2 = P2.x - sc * D2.x;
                }
                sum[o][0] += 0.2f * P0.x + 0.8f * s0;
                sum[o][1] += 0.2f * P1.x + 0.8f * s1;
                sum[o][2] += 0.2f * P2.x + 0.8f * s2;
            }
            {
                float dot = P0.y * D0.y + P1.y * D1.y + P2.y * D2.y;
                float s0, s1, s2;
                if (dot >= 0.f) { s0 = P0.y; s1 = P1.y; s2 = P2.y; }
                else {
                    float sc = dot * invB;
                    s0 = P0.y - sc * D0.y; s1 = P1.y - sc * D1.y; s2 = P2.y - sc * D2.y;
                }
                sum[o][0] += 0.2f * P0.y + 0.8f * s0;
                sum[o][1] += 0.2f * P1.y + 0.8f * s1;
                sum[o][2] += 0.2f * P2.y + 0.8f * s2;
            }
        }
    }
    #pragma unroll
    for (int o = 0; o < OT; o++)
        #pragma unroll
        for (int dd = 0; dd < 3; dd++) {
            float v = sum[o][dd];
            #pragma unroll
            for (int s = 16; s; s >>= 1) v += __shfl_down_sync(0xffffffffu, v, s);
            if ((tid & 31) == 0) atomicAdd(&sacc[o * 3 + dd], v);
        }
    __syncthreads();
    if (tid < OT * 3) out[b * 1023 + o0 * 3 + tid] = sacc[tid] * (1.f / NPT);
}

// ================= launch =================
static constexpr size_t ymap_smem(int CIN, int COUT)
{
    return (size_t)(4 * CIN * COUT + 3 * CIN * 32) * 4;
}
static constexpr size_t knn_smem(int D)
{
    return (size_t)16 * NPT * 4 + (size_t)D * 8 * 8;
}

// per-layer launch helper macro: knn halves on s0/s2, ymap on s1, pair halves
#define LAYER(D_, CIN_, COUT_, P_, src, ctot, coff, ooff, Wfp, Wdp)                          \
    do {                                                                                     \
        cudaEventRecord(evA, 0);                                                             \
        cudaStreamWaitEvent(s1, evA, 0);                                                     \
        cudaStreamWaitEvent(s2, evA, 0);                                                     \
        ymap_kernel<CIN_, COUT_><<<YG, 256, ymap_smem(CIN_, COUT_), s1>>>(src, ctot, coff,   \
                                                                          Wfp, Wdp);         \
        cudaEventRecord(evY, s1);                                                            \
        knn_kernel<D_><<<KHALF, 512, knn_smem(D_)>>>(src, ctot, coff, 0);                    \
        knn_kernel<D_><<<KHALF, 512, knn_smem(D_), s2>>>(src, ctot, coff, KHALF);            \
        cudaStreamWaitEvent(0, evY, 0);                                                      \
        cudaStreamWaitEvent(s2, evY, 0);                                                     \
        pair_kernel<COUT_, P_><<<HALFPT / P_, COUT_ * P_>>>(ooff, 0);                        \
        pair_kernel<COUT_, P_><<<HALFPT / P_, COUT_ * P_, 0, s2>>>(ooff, HALFPT);            \
        cudaEventRecord(evP, s2);                                                            \
        cudaStreamWaitEvent(0, evP, 0);                                                     \
    } while (0)

extern "C" void kernel_launch(void* const* d_in, const int* in_sizes, int n_in,
                              void* d_out, int out_size)
{
    const float* x   = (const float*)d_in[0];
    const float* Wf0 = (const float*)d_in[1];
    const float* Wd0 = (const float*)d_in[2];
    const float* Wf1 = (const float*)d_in[3];
    const float* Wd1 = (const float*)d_in[4];
    const float* Wf2 = (const float*)d_in[5];
    const float* Wd2 = (const float*)d_in[6];
    const float* Wf3 = (const float*)d_in[7];
    const float* Wd3 = (const float*)d_in[8];
    const float* Wf4 = (const float*)d_in[9];
    const float* Wd4 = (const float*)d_in[10];
    float* out = (float*)d_out;

    float* feat = nullptr;
    cudaGetSymbolAddress((void**)&feat, g_feat);

    static cudaStream_t s1, s2;
    static cudaEvent_t evA, evY, evP;
    static bool init_done = false;
    if (!init_done) {
        cudaStreamCreateWithFlags(&s1, cudaStreamNonBlocking);
        cudaStreamCreateWithFlags(&s2, cudaStreamNonBlocking);
        cudaEventCreateWithFlags(&evA, cudaEventDisableTiming);
        cudaEventCreateWithFlags(&evY, cudaEventDisableTiming);
        cudaEventCreateWithFlags(&evP, cudaEventDisableTiming);
        cudaFuncSetAttribute(ymap_kernel<42, 85>,
                             cudaFuncAttributeMaxDynamicSharedMemorySize,
                             (int)ymap_smem(42, 85));
        cudaFuncSetAttribute(knn_kernel<3>,
                             cudaFuncAttributeMaxDynamicSharedMemorySize,
                             (int)knn_smem(3));
        cudaFuncSetAttribute(knn_kernel<63>,
                             cudaFuncAttributeMaxDynamicSharedMemorySize,
                             (int)knn_smem(63));
        cudaFuncSetAttribute(knn_kernel<126>,
                             cudaFuncAttributeMaxDynamicSharedMemorySize,
                             (int)knn_smem(126));
        init_done = true;
    }

    const int KHALF = BATCH * (NPT / 16) / 2;   // 256 blocks per half
    const int YG    = TOTPT / 32;               // 256

    // layer 0 : CIN=1,  D=3,   out=21 -> feat[0:21)
    LAYER(3,   1,  21, 16, x,    1,    0,  0,  Wf0, Wd0);
    // layer 1 : CIN=21, D=63,  out=21 -> feat[21:42)
    LAYER(63,  21, 21, 16, feat, CTOT, 0,  21, Wf1, Wd1);
    // layer 2 : CIN=21, D=63,  out=42 -> feat[42:84)
    LAYER(63,  21, 42, 8,  feat, CTOT, 21, 42, Wf2, Wd2);
    // layer 3 : CIN=42, D=126, out=85 -> feat[84:169)
    LAYER(126, 42, 85, 4,  feat, CTOT, 42, 84, Wf3, Wd3);

    // final VN layer on concat [0:169) + mean over N
    final_kernel<<<BATCH * 31, 256>>>(Wf4, Wd4, out);
}

// round 9
// speedup vs baseline: 1.0353x; 1.0353x over previous
#include <cuda_runtime.h>
#include <cfloat>

#define BATCH 8
#define NPT   1024
#define KNN   20
#define EPSV  1e-6f
#define CTOT  169   // 21+21+42+85 concat channels
#define MAXCOUT 85
#define TOTPT (BATCH * NPT)

typedef unsigned long long u64;

// ---- packed f32x2 helpers (sm_10x FFMA2) ----
__device__ __forceinline__ u64 pk2(float lo, float hi) {
    u64 r; asm("mov.b64 %0,{%1,%2};" : "=l"(r) : "f"(lo), "f"(hi)); return r;
}
__device__ __forceinline__ void fma2(u64& d, u64 a, u64 b) {
    asm("fma.rn.f32x2 %0,%1,%2,%0;" : "+l"(d) : "l"(a), "l"(b));
}
__device__ __forceinline__ float2 up2(u64 v) {
    float2 r; asm("mov.b64 {%0,%1},%2;" : "=f"(r.x), "=f"(r.y) : "l"(v)); return r;
}
// monotone float -> uint (order-preserving)
__device__ __forceinline__ unsigned ford(float v) {
    unsigned u = __float_as_uint(v);
    return (u & 0x80000000u) ? ~u : (u | 0x80000000u);
}

// -------- scratch (no allocations allowed) --------
__device__ float  g_feat[BATCH * CTOT * 3 * NPT];        // [B][169][3][N]
__device__ int    g_idx[BATCH * NPT * KNN];
__device__ float4 g_yp [BATCH * NPT * MAXCOUT * 2];      // [pt][o]: {p0,d0,p1,d1},{p2,d2,-,-}
__device__ float2 g_cmb[BATCH * NPT * MAXCOUT * 3];      // [pt][o][f] {pc-yf, dc-yd}
__device__ float  g_pd [BATCH * 342 * 3 * NPT];          // partial final sums [b][o(341=d)][f][n]

// ================= knn (fused xx) + warp-parallel top-k (R7 version) =================
template <int D>
__global__ __launch_bounds__(256, 2)
void knn_kernel(const float* __restrict__ cur, int Ctot, int coff)
{
    const int TI = 16;
    extern __shared__ float smraw[];
    float (*sdist)[NPT] = (float(*)[NPT])smraw;          // [TI][NPT]
    u64   (*sxp)[8]     = (u64(*)[8])(smraw + TI * NPT); // [D][8] query rowpairs

    int b  = blockIdx.x / (NPT / TI);
    int i0 = (blockIdx.x % (NPT / TI)) * TI;
    int tid = threadIdx.x;
    const float* base = cur + (size_t)(b * Ctot + coff) * 3 * NPT;

    for (int f = tid; f < D; f += 256) {
        #pragma unroll
        for (int rp = 0; rp < 8; rp++) {
            float qa = base[f * NPT + i0 + 2 * rp];
            float qb = base[f * NPT + i0 + 2 * rp + 1];
            sxp[f][rp] = pk2(qa, qb);
        }
    }
    __syncthreads();

    {
        int j0 = tid * 4;
        u64 acc[8][4];
        float xx[4] = {0.f, 0.f, 0.f, 0.f};
        #pragma unroll
        for (int rp = 0; rp < 8; rp++)
            #pragma unroll
            for (int jj = 0; jj < 4; jj++) acc[rp][jj] = 0ull;

        #pragma unroll 2
        for (int f = 0; f < D; f++) {
            float4 xv = *(const float4*)(base + f * NPT + j0);
            u64 xp0 = pk2(xv.x, xv.x), xp1 = pk2(xv.y, xv.y);
            u64 xp2 = pk2(xv.z, xv.z), xp3 = pk2(xv.w, xv.w);
            u64 q[8];
            #pragma unroll
            for (int rp = 0; rp < 8; rp++) q[rp] = sxp[f][rp];
            #pragma unroll
            for (int rp = 0; rp < 8; rp++) {
                fma2(acc[rp][0], q[rp], xp0);
                fma2(acc[rp][1], q[rp], xp1);
                fma2(acc[rp][2], q[rp], xp2);
                fma2(acc[rp][3], q[rp], xp3);
            }
            xx[0] = fmaf(xv.x, xv.x, xx[0]);
            xx[1] = fmaf(xv.y, xv.y, xx[1]);
            xx[2] = fmaf(xv.z, xv.z, xx[2]);
            xx[3] = fmaf(xv.w, xv.w, xx[3]);
        }
        #pragma unroll
        for (int rp = 0; rp < 8; rp++) {
            float4 lo, hi;
            float2 v0 = up2(acc[rp][0]), v1 = up2(acc[rp][1]);
            float2 v2 = up2(acc[rp][2]), v3 = up2(acc[rp][3]);
            lo.x = 2.f * v0.x - xx[0]; hi.x = 2.f * v0.y - xx[0];
            lo.y = 2.f * v1.x - xx[1]; hi.y = 2.f * v1.y - xx[1];
            lo.z = 2.f * v2.x - xx[2]; hi.z = 2.f * v2.y - xx[2];
            lo.w = 2.f * v3.x - xx[3]; hi.w = 2.f * v3.y - xx[3];
            *(float4*)&sdist[2 * rp][j0]     = lo;
            *(float4*)&sdist[2 * rp + 1][j0] = hi;
        }
    }
    __syncthreads();

    // top-k: warp w handles rows 2w, 2w+1 with interleaved chains.
    int w = tid >> 5, lane = tid & 31;
    float* row0 = sdist[2 * w];
    float* row1 = sdist[2 * w + 1];
    int ob0 = (b * NPT + i0 + 2 * w) * KNN;
    int ob1 = ob0 + KNN;

    unsigned ck0, ck1; int ci0, ci1;
    {
        float lb0 = -FLT_MAX, lb1 = -FLT_MAX;
        int li0 = 0x7fffffff, li1 = 0x7fffffff;
        #pragma unroll 8
        for (int t = 0; t < 32; t++) {
            float v0 = row0[lane + 32 * t];
            float v1 = row1[lane + 32 * t];
            if (v0 > lb0) { lb0 = v0; li0 = lane + 32 * t; }
            if (v1 > lb1) { lb1 = v1; li1 = lane + 32 * t; }
        }
        ck0 = ford(lb0); ci0 = li0;
        ck1 = ford(lb1); ci1 = li1;
    }
    for (int it = 0; it < KNN; it++) {
        unsigned mx0 = __reduce_max_sync(0xffffffffu, ck0);
        unsigned mx1 = __reduce_max_sync(0xffffffffu, ck1);
        int wb0 = __reduce_min_sync(0xffffffffu, (ck0 == mx0) ? ci0 : 0x7fffffff);
        int wb1 = __reduce_min_sync(0xffffffffu, (ck1 == mx1) ? ci1 : 0x7fffffff);
        if (lane == 0) { g_idx[ob0 + it] = wb0; g_idx[ob1 + it] = wb1; }
        int own0 = wb0 & 31, own1 = wb1 & 31;
        if (lane == (wb0 >> 5)) row0[wb0] = -FLT_MAX;
        if (lane == (wb1 >> 5)) row1[wb1] = -FLT_MAX;
        float v0 = row0[own0 + 32 * lane];
        float v1 = row1[own1 + 32 * lane];
        unsigned k0 = ford(v0), k1 = ford(v1);
        unsigned m0 = __reduce_max_sync(0xffffffffu, k0);
        unsigned m1 = __reduce_max_sync(0xffffffffu, k1);
        int r0 = __reduce_min_sync(0xffffffffu, (k0 == m0) ? (own0 + 32 * lane) : 0x7fffffff);
        int r1 = __reduce_min_sync(0xffffffffu, (k1 == m1) ? (own1 + 32 * lane) : 0x7fffffff);
        if (lane == own0) { ck0 = m0; ci0 = r0; }
        if (lane == own1) { ck1 = m1; ci1 = r1; }
    }
}

// ================= per-point linear maps =================
template <int CIN, int COUT>
__global__ void ymap_kernel(const float* __restrict__ cur, int Ctot, int coff,
                            const float* __restrict__ Wf, const float* __restrict__ Wd)
{
    const int IN2 = 2 * CIN;
    extern __shared__ float sm[];
    float4* sW = (float4*)sm;                 // [CIN][COUT] {wfL,wdL,wfR,wdR}
    float*  sx = sm + 4 * CIN * COUT;         // [3*CIN][32]

    int tid = threadIdx.x;
    int nn = tid & 31, og = tid >> 5;
    int pt0 = blockIdx.x * 32;
    int b = pt0 >> 10, n0 = pt0 & (NPT - 1);
    const float* base = cur + (size_t)(b * Ctot + coff) * 3 * NPT;

    for (int t = tid; t < CIN * COUT; t += blockDim.x) {
        int c = t / COUT, o = t - c * COUT;
        sW[t] = make_float4(Wf[o * IN2 + c], Wd[o * IN2 + c],
                            Wf[o * IN2 + CIN + c], Wd[o * IN2 + CIN + c]);
    }
    for (int t = tid; t < 3 * CIN * 32; t += blockDim.x) {
        int row = t >> 5, col = t & 31;
        sx[t] = base[row * NPT + n0 + col];
    }
    __syncthreads();

    int pt = pt0 + nn;
    for (int o = og; o < COUT; o += 8) {
        u64 accL0 = 0ull, accL1 = 0ull, accL2 = 0ull;
        u64 accR0 = 0ull, accR1 = 0ull, accR2 = 0ull;
        for (int c = 0; c < CIN; c++) {
            float4 w = sW[c * COUT + o];
            u64 wl = pk2(w.x, w.y);
            u64 wr = pk2(w.z, w.w);
            float x0 = sx[(c * 3 + 0) * 32 + nn];
            float x1 = sx[(c * 3 + 1) * 32 + nn];
            float x2 = sx[(c * 3 + 2) * 32 + nn];
            u64 p0 = pk2(x0, x0), p1 = pk2(x1, x1), p2 = pk2(x2, x2);
            fma2(accL0, wl, p0); fma2(accR0, wr, p0);
            fma2(accL1, wl, p1); fma2(accR1, wr, p1);
            fma2(accL2, wl, p2); fma2(accR2, wr, p2);
        }
        float2 l0 = up2(accL0), l1 = up2(accL1), l2 = up2(accL2);
        float2 r0 = up2(accR0), r1 = up2(accR1), r2 = up2(accR2);
        float4* yo = g_yp + ((size_t)pt * COUT + o) * 2;
        yo[0] = make_float4(l0.x, l0.y, l1.x, l1.y);
        yo[1] = make_float4(l2.x, l2.y, 0.f, 0.f);
        float2* co = g_cmb + ((size_t)pt * COUT + o) * 3;
        co[0] = make_float2(r0.x - l0.x, r0.y - l0.y);
        co[1] = make_float2(r1.x - l1.x, r1.y - l1.y);
        co[2] = make_float2(r2.x - l2.x, r2.y - l2.y);
    }
}

// ================= gather + leaky combine + mean over k =================
template <int COUT, int P, int TPB>
__global__ void pair_kernel(int ooff)
{
    __shared__ int sidx[P][KNN];
    int tid = threadIdx.x;
    int pt0 = blockIdx.x * P;

    for (int t = tid; t < P * KNN; t += TPB) {
        int p = t / KNN;
        if (pt0 + p < TOTPT) sidx[p][t - p * KNN] = g_idx[(pt0 + p) * KNN + (t - p * KNN)];
    }
    __syncthreads();

    int ln = tid / COUT, o = tid - ln * COUT;
    int pt = pt0 + ln;
    if (ln >= P || pt >= TOTPT) return;
    int b = pt >> 10, n = pt & (NPT - 1);

    const float2* cmb = g_cmb + ((size_t)pt * COUT + o) * 3;
    float2 c0 = cmb[0], c1 = cmb[1], c2 = cmb[2];

    float a0 = 0.f, a1 = 0.f, a2 = 0.f;
    #pragma unroll 5
    for (int j = 0; j < KNN; j++) {
        int nj = sidx[ln][j];
        const float4* y = g_yp + (((size_t)(b << 10) + nj) * COUT + o) * 2;
        float4 A  = y[0];
        float2 Bv = *(const float2*)(y + 1);
        float P0 = A.x  + c0.x, D0 = A.y  + c0.y;
        float P1 = A.z  + c1.x, D1 = A.w  + c1.y;
        float P2 = Bv.x + c2.x, D2 = Bv.y + c2.y;
        float dot = P0 * D0 + P1 * D1 + P2 * D2;
        float dsq = D0 * D0 + D1 * D1 + D2 * D2;
        float s = dot / (dsq + EPSV);
        float s0, s1, s2;
        if (dot >= 0.f) { s0 = P0; s1 = P1; s2 = P2; }
        else { s0 = P0 - s * D0; s1 = P1 - s * D1; s2 = P2 - s * D2; }
        a0 += 0.2f * P0 + 0.8f * s0;
        a1 += 0.2f * P1 + 0.8f * s1;
        a2 += 0.2f * P2 + 0.8f * s2;
    }
    const float invK = 1.f / KNN;
    float* fo = g_feat + (((size_t)b * CTOT + ooff + o) * 3) * NPT + n;
    fo[0 * NPT] = a0 * invK;
    fo[1 * NPT] = a1 * invK;
    fo[2 * NPT] = a2 * invK;
}

// ========== final VN layer, part 1: partial sums over c in [0,84) ==========
__global__ void final_part(const float* __restrict__ Wf, const float* __restrict__ Wd)
{
    const int OT = 11, CI = CTOT, CP = 84;
    __shared__ u64 sWfp[OT * CP];
    __shared__ u64 sWdp[CP];
    int b  = blockIdx.x / 31;
    int o0 = (blockIdx.x % 31) * OT;
    int tid = threadIdx.x;

    for (int t = tid; t < OT * CP; t += 256) {
        int o = t / CP, c = t - o * CP;
        float w = Wf[(o0 + o) * CI + c];
        sWfp[t] = pk2(w, w);
    }
    for (int t = tid; t < CP; t += 256) { float w = Wd[t]; sWdp[t] = pk2(w, w); }
    __syncthreads();

    const float* fb = g_feat + (size_t)b * CTOT * 3 * NPT;
    float* pb = g_pd + (size_t)b * 342 * 3 * NPT;
    for (int it = 0; it < 2; it++) {
        int n = 2 * (tid + it * 256);
        u64 p0[OT], p1[OT], p2[OT];
        u64 d0 = 0ull, d1 = 0ull, d2 = 0ull;
        #pragma unroll
        for (int o = 0; o < OT; o++) { p0[o] = p1[o] = p2[o] = 0ull; }

        for (int c = 0; c < CP; c++) {
            u64 x0 = *(const u64*)(fb + (c * 3 + 0) * NPT + n);
            u64 x1 = *(const u64*)(fb + (c * 3 + 1) * NPT + n);
            u64 x2 = *(const u64*)(fb + (c * 3 + 2) * NPT + n);
            u64 wd = sWdp[c];
            fma2(d0, wd, x0); fma2(d1, wd, x1); fma2(d2, wd, x2);
            #pragma unroll
            for (int o = 0; o < OT; o++) {
                u64 wf = sWfp[o * CP + c];
                fma2(p0[o], wf, x0); fma2(p1[o], wf, x1); fma2(p2[o], wf, x2);
            }
        }
        #pragma unroll
        for (int o = 0; o < OT; o++) {
            *(u64*)&pb[((o0 + o) * 3 + 0) * NPT + n] = p0[o];
            *(u64*)&pb[((o0 + o) * 3 + 1) * NPT + n] = p1[o];
            *(u64*)&pb[((o0 + o) * 3 + 2) * NPT + n] = p2[o];
        }
        if (o0 == 0) {
            *(u64*)&pb[(341 * 3 + 0) * NPT + n] = d0;
            *(u64*)&pb[(341 * 3 + 1) * NPT + n] = d1;
            *(u64*)&pb[(341 * 3 + 2) * NPT + n] = d2;
        }
    }
}

// ========== final VN layer, part 2: c in [84,169), leaky + mean over N ==========
__global__ void final_rest(const float* __restrict__ Wf, const float* __restrict__ Wd,
                           float* __restrict__ out)
{
    const int OT = 11, CI = CTOT, CP = 84, CR = CI - CP;   // 85
    __shared__ u64   sWfp[OT * CR];
    __shared__ u64   sWdp[CR];
    __shared__ float sacc[OT * 3];
    int b  = blockIdx.x / 31;
    int o0 = (blockIdx.x % 31) * OT;
    int tid = threadIdx.x;

    for (int t = tid; t < OT * CR; t += 256) {
        int o = t / CR, c = t - o * CR;
        float w = Wf[(o0 + o) * CI + CP + c];
        sWfp[t] = pk2(w, w);
    }
    for (int t = tid; t < CR; t += 256) { float w = Wd[CP + t]; sWdp[t] = pk2(w, w); }
    if (tid < OT * 3) sacc[tid] = 0.f;
    __syncthreads();

    float sum[OT][3];
    #pragma unroll
    for (int o = 0; o < OT; o++) { sum[o][0] = sum[o][1] = sum[o][2] = 0.f; }

    const float* fb = g_feat + (size_t)b * CTOT * 3 * NPT;
    const float* pb = g_pd + (size_t)b * 342 * 3 * NPT;
    for (int it = 0; it < 2; it++) {
        int n = 2 * (tid + it * 256);
        u64 p0[OT], p1[OT], p2[OT];
        #pragma unroll
        for (int o = 0; o < OT; o++) {
            p0[o] = *(const u64*)&pb[((o0 + o) * 3 + 0) * NPT + n];
            p1[o] = *(const u64*)&pb[((o0 + o) * 3 + 1) * NPT + n];
            p2[o] = *(const u64*)&pb[((o0 + o) * 3 + 2) * NPT + n];
        }
        u64 d0 = *(const u64*)&pb[(341 * 3 + 0) * NPT + n];
        u64 d1 = *(const u64*)&pb[(341 * 3 + 1) * NPT + n];
        u64 d2 = *(const u64*)&pb[(341 * 3 + 2) * NPT + n];

        for (int c = 0; c < CR; c++) {
            u64 x0 = *(const u64*)(fb + ((CP + c) * 3 + 0) * NPT + n);
            u64 x1 = *(const u64*)(fb + ((CP + c) * 3 + 1) * NPT + n);
            u64 x2 = *(const u64*)(fb + ((CP + c) * 3 + 2) * NPT + n);
            u64 wd = sWdp[c];
            fma2(d0, wd, x0); fma2(d1, wd, x1); fma2(d2, wd, x2);
            #pragma unroll
            for (int o = 0; o < OT; o++) {
                u64 wf = sWfp[o * CR + c];
                fma2(p0[o], wf, x0); fma2(p1[o], wf, x1); fma2(p2[o], wf, x2);
            }
        }
        float2 D0 = up2(d0), D1 = up2(d1), D2 = up2(d2);
        float invA = 1.f / (D0.x * D0.x + D1.x * D1.x + D2.x * D2.x + EPSV);
        float invB = 1.f / (D0.y * D0.y + D1.y * D1.y + D2.y * D2.y + EPSV);
        #pragma unroll
        for (int o = 0; o < OT; o++) {
            float2 P0 = up2(p0[o]), P1 = up2(p1[o]), P2 = up2(p2[o]);
            {
                float dot = P0.x * D0.x + P1.x * D1.x + P2.x * D2.x;
                float s0, s1, s2;
                if (dot >= 0.f) { s0 = P0.x; s1 = P1.x; s2 = P2.x; }
                else {
                    float sc = dot * invA;
                    s0 = P0.x - sc * D0.x; s1 = P1.x - sc * D1.x; s2 = P2.x - sc * D2.x;
                }
                sum[o][0] += 0.2f * P0.x + 0.8f * s0;
                sum[o][1] += 0.2f * P1.x + 0.8f * s1;
                sum[o][2] += 0.2f * P2.x + 0.8f * s2;
            }
            {
                float dot = P0.y * D0.y + P1.y * D1.y + P2.y * D2.y;
                float s0, s1, s2;
                if (dot >= 0.f) { s0 = P0.y; s1 = P1.y; s2 = P2.y; }
                else {
                    float sc = dot * invB;
                    s0 = P0.y - sc * D0.y; s1 = P1.y - sc * D1.y; s2 = P2.y - sc * D2.y;
                }
                sum[o][0] += 0.2f * P0.y + 0.8f * s0;
                sum[o][1] += 0.2f * P1.y + 0.8f * s1;
                sum[o][2] += 0.2f * P2.y + 0.8f * s2;
            }
        }
    }
    #pragma unroll
    for (int o = 0; o < OT; o++)
        #pragma unroll
        for (int dd = 0; dd < 3; dd++) {
            float v = sum[o][dd];
            #pragma unroll
            for (int s = 16; s; s >>= 1) v += __shfl_down_sync(0xffffffffu, v, s);
            if ((tid & 31) == 0) atomicAdd(&sacc[o * 3 + dd], v);
        }
    __syncthreads();
    if (tid < OT * 3) out[b * 1023 + o0 * 3 + tid] = sacc[tid] * (1.f / NPT);
}

// ================= launch =================
static constexpr size_t ymap_smem(int CIN, int COUT)
{
    return (size_t)(4 * CIN * COUT + 3 * CIN * 32) * 4;
}
static constexpr size_t knn_smem(int D)
{
    return (size_t)16 * NPT * 4 + (size_t)D * 8 * 8;
}

extern "C" void kernel_launch(void* const* d_in, const int* in_sizes, int n_in,
                              void* d_out, int out_size)
{
    const float* x   = (const float*)d_in[0];
    const float* Wf0 = (const float*)d_in[1];
    const float* Wd0 = (const float*)d_in[2];
    const float* Wf1 = (const float*)d_in[3];
    const float* Wd1 = (const float*)d_in[4];
    const float* Wf2 = (const float*)d_in[5];
    const float* Wd2 = (const float*)d_in[6];
    const float* Wf3 = (const float*)d_in[7];
    const float* Wd3 = (const float*)d_in[8];
    const float* Wf4 = (const float*)d_in[9];
    const float* Wd4 = (const float*)d_in[10];
    float* out = (float*)d_out;

    float* feat = nullptr;
    cudaGetSymbolAddress((void**)&feat, g_feat);

    static cudaStream_t s1;
    static cudaEvent_t evF, evJ;
    static bool init_done = false;
    if (!init_done) {
        cudaStreamCreateWithFlags(&s1, cudaStreamNonBlocking);
        cudaEventCreateWithFlags(&evF, cudaEventDisableTiming);
        cudaEventCreateWithFlags(&evJ, cudaEventDisableTiming);
        cudaFuncSetAttribute(ymap_kernel<42, 85>,
                             cudaFuncAttributeMaxDynamicSharedMemorySize,
                             (int)ymap_smem(42, 85));
        cudaFuncSetAttribute(knn_kernel<3>,
                             cudaFuncAttributeMaxDynamicSharedMemorySize,
                             (int)knn_smem(3));
        cudaFuncSetAttribute(knn_kernel<63>,
                             cudaFuncAttributeMaxDynamicSharedMemorySize,
                             (int)knn_smem(63));
        cudaFuncSetAttribute(knn_kernel<126>,
                             cudaFuncAttributeMaxDynamicSharedMemorySize,
                             (int)knn_smem(126));
        init_done = true;
    }

    const int KNNG = BATCH * (NPT / 16);     // 512
    const int YG   = TOTPT / 32;             // 256

    // ---- layer 0 : CIN=1, D=3, out=21 -> feat[0:21) ----
    cudaEventRecord(evF, 0);
    cudaStreamWaitEvent(s1, evF, 0);
    ymap_kernel<1, 21><<<YG, 256, ymap_smem(1, 21), s1>>>(x, 1, 0, Wf0, Wd0);
    cudaEventRecord(evJ, s1);
    knn_kernel<3><<<KNNG, 256, knn_smem(3)>>>(x, 1, 0);
    cudaStreamWaitEvent(0, evJ, 0);
    pair_kernel<21, 12, 256><<<(TOTPT + 11) / 12, 256>>>(0);

    // ---- layer 1 : CIN=21, D=63, out=21 -> feat[21:42) ----
    cudaEventRecord(evF, 0);
    cudaStreamWaitEvent(s1, evF, 0);
    ymap_kernel<21, 21><<<YG, 256, ymap_smem(21, 21), s1>>>(feat, CTOT, 0, Wf1, Wd1);
    cudaEventRecord(evJ, s1);
    knn_kernel<63><<<KNNG, 256, knn_smem(63)>>>(feat, CTOT, 0);
    cudaStreamWaitEvent(0, evJ, 0);
    pair_kernel<21, 12, 256><<<(TOTPT + 11) / 12, 256>>>(21);

    // ---- layer 2 : CIN=21, D=63, out=42 -> feat[42:84) ----
    cudaEventRecord(evF, 0);
    cudaStreamWaitEvent(s1, evF, 0);
    ymap_kernel<21, 42><<<YG, 256, ymap_smem(21, 42), s1>>>(feat, CTOT, 21, Wf2, Wd2);
    cudaEventRecord(evJ, s1);
    knn_kernel<63><<<KNNG, 256, knn_smem(63)>>>(feat, CTOT, 21);
    cudaStreamWaitEvent(0, evJ, 0);
    pair_kernel<42, 6, 256><<<(TOTPT + 5) / 6, 256>>>(42);

    // ---- layer 3 : CIN=42, D=126, out=85 -> feat[84:169) ----
    // side stream also computes final partial sums over c in [0,84) (ready after pair2)
    cudaEventRecord(evF, 0);
    cudaStreamWaitEvent(s1, evF, 0);
    ymap_kernel<42, 85><<<YG, 256, ymap_smem(42, 85), s1>>>(feat, CTOT, 42, Wf3, Wd3);
    final_part<<<BATCH * 31, 256, 0, s1>>>(Wf4, Wd4);
    cudaEventRecord(evJ, s1);
    knn_kernel<126><<<KNNG, 256, knn_smem(126)>>>(feat, CTOT, 42);
    cudaStreamWaitEvent(0, evJ, 0);
    pair_kernel<85, 3, 256><<<(TOTPT + 2) / 3, 256>>>(84);

    // ---- final VN layer remainder c in [84,169), leaky + mean over N ----
    final_rest<<<BATCH * 31, 256>>>(Wf4, Wd4, out);
}

// round 10
// speedup vs baseline: 1.0535x; 1.0175x over previous
#include <cuda_runtime.h>
#include <cfloat>

#define BATCH 8
#define NPT   1024
#define KNN   20
#define EPSV  1e-6f
#define CTOT  169   // 21+21+42+85 concat channels
#define MAXCOUT 85
#define TOTPT (BATCH * NPT)

typedef unsigned long long u64;

// ---- packed f32x2 helpers (sm_10x FFMA2) ----
__device__ __forceinline__ u64 pk2(float lo, float hi) {
    u64 r; asm("mov.b64 %0,{%1,%2};" : "=l"(r) : "f"(lo), "f"(hi)); return r;
}
__device__ __forceinline__ void fma2(u64& d, u64 a, u64 b) {
    asm("fma.rn.f32x2 %0,%1,%2,%0;" : "+l"(d) : "l"(a), "l"(b));
}
__device__ __forceinline__ float2 up2(u64 v) {
    float2 r; asm("mov.b64 {%0,%1},%2;" : "=f"(r.x), "=f"(r.y) : "l"(v)); return r;
}
// monotone float -> uint (order-preserving)
__device__ __forceinline__ unsigned ford(float v) {
    unsigned u = __float_as_uint(v);
    return (u & 0x80000000u) ? ~u : (u | 0x80000000u);
}

// -------- scratch (no allocations allowed) --------
__device__ float  g_feat[BATCH * CTOT * 3 * NPT];        // [B][169][3][N]
__device__ int    g_idx[BATCH * NPT * KNN];
__device__ float4 g_ypA[TOTPT * MAXCOUT];                // [pt][o] {p0,d0,p1,d1}
__device__ float2 g_ypB[TOTPT * MAXCOUT];                // [pt][o] {p2,d2}
__device__ float2 g_cmb[BATCH * NPT * MAXCOUT * 3];      // [pt][o][f] {pc-yf, dc-yd}
__device__ float  g_pd [BATCH * 342 * 3 * NPT];          // partial final sums

// ================= knn (fused xx) + warp-parallel top-k =================
// key_j = 2*dot(xi,xj) - xx_j  (row-constant xx_i dropped; ranking unchanged)
// TI=16 rows/block, 256 threads, distance-2 register prefetch on xv.
template <int D>
__global__ __launch_bounds__(256, 2)
void knn_kernel(const float* __restrict__ cur, int Ctot, int coff)
{
    const int TI = 16;
    extern __shared__ float smraw[];
    float (*sdist)[NPT] = (float(*)[NPT])smraw;          // [TI][NPT]
    u64   (*sxp)[8]     = (u64(*)[8])(smraw + TI * NPT); // [D][8] query rowpairs

    int b  = blockIdx.x / (NPT / TI);
    int i0 = (blockIdx.x % (NPT / TI)) * TI;
    int tid = threadIdx.x;
    const float* base = cur + (size_t)(b * Ctot + coff) * 3 * NPT;

    for (int f = tid; f < D; f += 256) {
        #pragma unroll
        for (int rp = 0; rp < 8; rp++) {
            float qa = base[f * NPT + i0 + 2 * rp];
            float qb = base[f * NPT + i0 + 2 * rp + 1];
            sxp[f][rp] = pk2(qa, qb);
        }
    }
    __syncthreads();

    // ---- distance phase: 4 contiguous j per thread, xv prefetched 2 ahead ----
    {
        int j0 = tid * 4;
        const float* bp = base + j0;
        u64 acc[8][4];
        float xx[4] = {0.f, 0.f, 0.f, 0.f};
        #pragma unroll
        for (int rp = 0; rp < 8; rp++)
            #pragma unroll
            for (int jj = 0; jj < 4; jj++) acc[rp][jj] = 0ull;

        float4 xv0 = *(const float4*)bp;
        float4 xv1 = *(const float4*)(bp + (D > 1 ? NPT : 0));

        #pragma unroll 2
        for (int f = 0; f < D; f++) {
            int fn = f + 2 < D ? f + 2 : D - 1;
            float4 nxt = *(const float4*)(bp + (size_t)fn * NPT);

            float4 xv = xv0;
            u64 xp0 = pk2(xv.x, xv.x), xp1 = pk2(xv.y, xv.y);
            u64 xp2 = pk2(xv.z, xv.z), xp3 = pk2(xv.w, xv.w);
            u64 q[8];
            #pragma unroll
            for (int rp = 0; rp < 8; rp++) q[rp] = sxp[f][rp];
            #pragma unroll
            for (int rp = 0; rp < 8; rp++) {
                fma2(acc[rp][0], q[rp], xp0);
                fma2(acc[rp][1], q[rp], xp1);
                fma2(acc[rp][2], q[rp], xp2);
                fma2(acc[rp][3], q[rp], xp3);
            }
            xx[0] = fmaf(xv.x, xv.x, xx[0]);
            xx[1] = fmaf(xv.y, xv.y, xx[1]);
            xx[2] = fmaf(xv.z, xv.z, xx[2]);
            xx[3] = fmaf(xv.w, xv.w, xx[3]);

            xv0 = xv1; xv1 = nxt;
        }
        #pragma unroll
        for (int rp = 0; rp < 8; rp++) {
            float4 lo, hi;
            float2 v0 = up2(acc[rp][0]), v1 = up2(acc[rp][1]);
            float2 v2 = up2(acc[rp][2]), v3 = up2(acc[rp][3]);
            lo.x = 2.f * v0.x - xx[0]; hi.x = 2.f * v0.y - xx[0];
            lo.y = 2.f * v1.x - xx[1]; hi.y = 2.f * v1.y - xx[1];
            lo.z = 2.f * v2.x - xx[2]; hi.z = 2.f * v2.y - xx[2];
            lo.w = 2.f * v3.x - xx[3]; hi.w = 2.f * v3.y - xx[3];
            *(float4*)&sdist[2 * rp][j0]     = lo;
            *(float4*)&sdist[2 * rp + 1][j0] = hi;
        }
    }
    __syncthreads();

    // ---- top-k: warp w handles rows 2w, 2w+1 with interleaved chains ----
    int w = tid >> 5, lane = tid & 31;
    float* row0 = sdist[2 * w];
    float* row1 = sdist[2 * w + 1];
    int ob0 = (b * NPT + i0 + 2 * w) * KNN;
    int ob1 = ob0 + KNN;

    unsigned ck0, ck1; int ci0, ci1;
    {
        float lb0 = -FLT_MAX, lb1 = -FLT_MAX;
        int li0 = 0x7fffffff, li1 = 0x7fffffff;
        #pragma unroll 8
        for (int t = 0; t < 32; t++) {
            float v0 = row0[lane + 32 * t];
            float v1 = row1[lane + 32 * t];
            if (v0 > lb0) { lb0 = v0; li0 = lane + 32 * t; }
            if (v1 > lb1) { lb1 = v1; li1 = lane + 32 * t; }
        }
        ck0 = ford(lb0); ci0 = li0;
        ck1 = ford(lb1); ci1 = li1;
    }
    for (int it = 0; it < KNN; it++) {
        unsigned mx0 = __reduce_max_sync(0xffffffffu, ck0);
        unsigned mx1 = __reduce_max_sync(0xffffffffu, ck1);
        int wb0 = __reduce_min_sync(0xffffffffu, (ck0 == mx0) ? ci0 : 0x7fffffff);
        int wb1 = __reduce_min_sync(0xffffffffu, (ck1 == mx1) ? ci1 : 0x7fffffff);
        if (lane == 0) { g_idx[ob0 + it] = wb0; g_idx[ob1 + it] = wb1; }
        int own0 = wb0 & 31, own1 = wb1 & 31;
        if (lane == (wb0 >> 5)) row0[wb0] = -FLT_MAX;
        if (lane == (wb1 >> 5)) row1[wb1] = -FLT_MAX;
        float v0 = row0[own0 + 32 * lane];
        float v1 = row1[own1 + 32 * lane];
        unsigned k0 = ford(v0), k1 = ford(v1);
        unsigned m0 = __reduce_max_sync(0xffffffffu, k0);
        unsigned m1 = __reduce_max_sync(0xffffffffu, k1);
        int r0 = __reduce_min_sync(0xffffffffu, (k0 == m0) ? (own0 + 32 * lane) : 0x7fffffff);
        int r1 = __reduce_min_sync(0xffffffffu, (k1 == m1) ? (own1 + 32 * lane) : 0x7fffffff);
        if (lane == own0) { ck0 = m0; ci0 = r0; }
        if (lane == own1) { ck1 = m1; ci1 = r1; }
    }
}

// ================= per-point linear maps =================
template <int CIN, int COUT>
__global__ void ymap_kernel(const float* __restrict__ cur, int Ctot, int coff,
                            const float* __restrict__ Wf, const float* __restrict__ Wd)
{
    const int IN2 = 2 * CIN;
    extern __shared__ float sm[];
    float4* sW = (float4*)sm;                 // [CIN][COUT] {wfL,wdL,wfR,wdR}
    float*  sx = sm + 4 * CIN * COUT;         // [3*CIN][32]

    int tid = threadIdx.x;
    int nn = tid & 31, og = tid >> 5;
    int pt0 = blockIdx.x * 32;
    int b = pt0 >> 10, n0 = pt0 & (NPT - 1);
    const float* base = cur + (size_t)(b * Ctot + coff) * 3 * NPT;

    for (int t = tid; t < CIN * COUT; t += blockDim.x) {
        int c = t / COUT, o = t - c * COUT;
        sW[t] = make_float4(Wf[o * IN2 + c], Wd[o * IN2 + c],
                            Wf[o * IN2 + CIN + c], Wd[o * IN2 + CIN + c]);
    }
    for (int t = tid; t < 3 * CIN * 32; t += blockDim.x) {
        int row = t >> 5, col = t & 31;
        sx[t] = base[row * NPT + n0 + col];
    }
    __syncthreads();

    int pt = pt0 + nn;
    for (int o = og; o < COUT; o += 8) {
        u64 accL0 = 0ull, accL1 = 0ull, accL2 = 0ull;
        u64 accR0 = 0ull, accR1 = 0ull, accR2 = 0ull;
        for (int c = 0; c < CIN; c++) {
            float4 w = sW[c * COUT + o];
            u64 wl = pk2(w.x, w.y);
            u64 wr = pk2(w.z, w.w);
            float x0 = sx[(c * 3 + 0) * 32 + nn];
            float x1 = sx[(c * 3 + 1) * 32 + nn];
            float x2 = sx[(c * 3 + 2) * 32 + nn];
            u64 p0 = pk2(x0, x0), p1 = pk2(x1, x1), p2 = pk2(x2, x2);
            fma2(accL0, wl, p0); fma2(accR0, wr, p0);
            fma2(accL1, wl, p1); fma2(accR1, wr, p1);
            fma2(accL2, wl, p2); fma2(accR2, wr, p2);
        }
        float2 l0 = up2(accL0), l1 = up2(accL1), l2 = up2(accL2);
        float2 r0 = up2(accR0), r1 = up2(accR1), r2 = up2(accR2);
        g_ypA[(size_t)pt * COUT + o] = make_float4(l0.x, l0.y, l1.x, l1.y);
        g_ypB[(size_t)pt * COUT + o] = make_float2(l2.x, l2.y);
        float2* co = g_cmb + ((size_t)pt * COUT + o) * 3;
        co[0] = make_float2(r0.x - l0.x, r0.y - l0.y);
        co[1] = make_float2(r1.x - l1.x, r1.y - l1.y);
        co[2] = make_float2(r2.x - l2.x, r2.y - l2.y);
    }
}

// ================= gather + leaky combine + mean over k =================
template <int COUT, int P, int TPB>
__global__ void pair_kernel(int ooff)
{
    __shared__ int sidx[P][KNN];
    int tid = threadIdx.x;
    int pt0 = blockIdx.x * P;

    for (int t = tid; t < P * KNN; t += TPB) {
        int p = t / KNN;
        if (pt0 + p < TOTPT) sidx[p][t - p * KNN] = g_idx[(pt0 + p) * KNN + (t - p * KNN)];
    }
    __syncthreads();

    int ln = tid / COUT, o = tid - ln * COUT;
    int pt = pt0 + ln;
    if (ln >= P || pt >= TOTPT) return;
    int b = pt >> 10, n = pt & (NPT - 1);

    const float2* cmb = g_cmb + ((size_t)pt * COUT + o) * 3;
    float2 c0 = cmb[0], c1 = cmb[1], c2 = cmb[2];

    float a0 = 0.f, a1 = 0.f, a2 = 0.f;
    #pragma unroll 5
    for (int j = 0; j < KNN; j++) {
        int nj = sidx[ln][j];
        size_t yi = ((size_t)(b << 10) + nj) * COUT + o;
        float4 A  = g_ypA[yi];
        float2 Bv = g_ypB[yi];
        float P0 = A.x  + c0.x, D0 = A.y  + c0.y;
        float P1 = A.z  + c1.x, D1 = A.w  + c1.y;
        float P2 = Bv.x + c2.x, D2 = Bv.y + c2.y;
        float dot = P0 * D0 + P1 * D1 + P2 * D2;
        float dsq = D0 * D0 + D1 * D1 + D2 * D2;
        float s = dot / (dsq + EPSV);
        float s0, s1, s2;
        if (dot >= 0.f) { s0 = P0; s1 = P1; s2 = P2; }
        else { s0 = P0 - s * D0; s1 = P1 - s * D1; s2 = P2 - s * D2; }
        a0 += 0.2f * P0 + 0.8f * s0;
        a1 += 0.2f * P1 + 0.8f * s1;
        a2 += 0.2f * P2 + 0.8f * s2;
    }
    const float invK = 1.f / KNN;
    float* fo = g_feat + (((size_t)b * CTOT + ooff + o) * 3) * NPT + n;
    fo[0 * NPT] = a0 * invK;
    fo[1 * NPT] = a1 * invK;
    fo[2 * NPT] = a2 * invK;
}

// ========== final VN layer, part 1: partial sums over c in [0,84) ==========
__global__ void final_part(const float* __restrict__ Wf, const float* __restrict__ Wd)
{
    const int OT = 11, CI = CTOT, CP = 84;
    __shared__ u64 sWfp[OT * CP];
    __shared__ u64 sWdp[CP];
    int b  = blockIdx.x / 31;
    int o0 = (blockIdx.x % 31) * OT;
    int tid = threadIdx.x;

    for (int t = tid; t < OT * CP; t += 256) {
        int o = t / CP, c = t - o * CP;
        float w = Wf[(o0 + o) * CI + c];
        sWfp[t] = pk2(w, w);
    }
    for (int t = tid; t < CP; t += 256) { float w = Wd[t]; sWdp[t] = pk2(w, w); }
    __syncthreads();

    const float* fb = g_feat + (size_t)b * CTOT * 3 * NPT;
    float* pb = g_pd + (size_t)b * 342 * 3 * NPT;
    for (int it = 0; it < 2; it++) {
        int n = 2 * (tid + it * 256);
        u64 p0[OT], p1[OT], p2[OT];
        u64 d0 = 0ull, d1 = 0ull, d2 = 0ull;
        #pragma unroll
        for (int o = 0; o < OT; o++) { p0[o] = p1[o] = p2[o] = 0ull; }

        for (int c = 0; c < CP; c++) {
            u64 x0 = *(const u64*)(fb + (c * 3 + 0) * NPT + n);
            u64 x1 = *(const u64*)(fb + (c * 3 + 1) * NPT + n);
            u64 x2 = *(const u64*)(fb + (c * 3 + 2) * NPT + n);
            u64 wd = sWdp[c];
            fma2(d0, wd, x0); fma2(d1, wd, x1); fma2(d2, wd, x2);
            #pragma unroll
            for (int o = 0; o < OT; o++) {
                u64 wf = sWfp[o * CP + c];
                fma2(p0[o], wf, x0); fma2(p1[o], wf, x1); fma2(p2[o], wf, x2);
            }
        }
        #pragma unroll
        for (int o = 0; o < OT; o++) {
            *(u64*)&pb[((o0 + o) * 3 + 0) * NPT + n] = p0[o];
            *(u64*)&pb[((o0 + o) * 3 + 1) * NPT + n] = p1[o];
            *(u64*)&pb[((o0 + o) * 3 + 2) * NPT + n] = p2[o];
        }
        if (o0 == 0) {
            *(u64*)&pb[(341 * 3 + 0) * NPT + n] = d0;
            *(u64*)&pb[(341 * 3 + 1) * NPT + n] = d1;
            *(u64*)&pb[(341 * 3 + 2) * NPT + n] = d2;
        }
    }
}

// ========== final VN layer, part 2: c in [84,169), leaky + mean over N ==========
__global__ void final_rest(const float* __restrict__ Wf, const float* __restrict__ Wd,
                           float* __restrict__ out)
{
    const int OT = 11, CI = CTOT, CP = 84, CR = CI - CP;   // 85
    __shared__ u64   sWfp[OT * CR];
    __shared__ u64   sWdp[CR];
    __shared__ float sacc[OT * 3];
    int b  = blockIdx.x / 31;
    int o0 = (blockIdx.x % 31) * OT;
    int tid = threadIdx.x;

    for (int t = tid; t < OT * CR; t += 256) {
        int o = t / CR, c = t - o * CR;
        float w = Wf[(o0 + o) * CI + CP + c];
        sWfp[t] = pk2(w, w);
    }
    for (int t = tid; t < CR; t += 256) { float w = Wd[CP + t]; sWdp[t] = pk2(w, w); }
    if (tid < OT * 3) sacc[tid] = 0.f;
    __syncthreads();

    float sum[OT][3];
    #pragma unroll
    for (int o = 0; o < OT; o++) { sum[o][0] = sum[o][1] = sum[o][2] = 0.f; }

    const float* fb = g_feat + (size_t)b * CTOT * 3 * NPT;
    const float* pb = g_pd + (size_t)b * 342 * 3 * NPT;
    for (int it = 0; it < 2; it++) {
        int n = 2 * (tid + it * 256);
        u64 p0[OT], p1[OT], p2[OT];
        #pragma unroll
        for (int o = 0; o < OT; o++) {
            p0[o] = *(const u64*)&pb[((o0 + o) * 3 + 0) * NPT + n];
            p1[o] = *(const u64*)&pb[((o0 + o) * 3 + 1) * NPT + n];
            p2[o] = *(const u64*)&pb[((o0 + o) * 3 + 2) * NPT + n];
        }
        u64 d0 = *(const u64*)&pb[(341 * 3 + 0) * NPT + n];
        u64 d1 = *(const u64*)&pb[(341 * 3 + 1) * NPT + n];
        u64 d2 = *(const u64*)&pb[(341 * 3 + 2) * NPT + n];

        for (int c = 0; c < CR; c++) {
            u64 x0 = *(const u64*)(fb + ((CP + c) * 3 + 0) * NPT + n);
            u64 x1 = *(const u64*)(fb + ((CP + c) * 3 + 1) * NPT + n);
            u64 x2 = *(const u64*)(fb + ((CP + c) * 3 + 2) * NPT + n);
            u64 wd = sWdp[c];
            fma2(d0, wd, x0); fma2(d1, wd, x1); fma2(d2, wd, x2);
            #pragma unroll
            for (int o = 0; o < OT; o++) {
                u64 wf = sWfp[o * CR + c];
                fma2(p0[o], wf, x0); fma2(p1[o], wf, x1); fma2(p2[o], wf, x2);
            }
        }
        float2 D0 = up2(d0), D1 = up2(d1), D2 = up2(d2);
        float invA = 1.f / (D0.x * D0.x + D1.x * D1.x + D2.x * D2.x + EPSV);
        float invB = 1.f / (D0.y * D0.y + D1.y * D1.y + D2.y * D2.y + EPSV);
        #pragma unroll
        for (int o = 0; o < OT; o++) {
            float2 P0 = up2(p0[o]), P1 = up2(p1[o]), P2 = up2(p2[o]);
            {
                float dot = P0.x * D0.x + P1.x * D1.x + P2.x * D2.x;
                float s0, s1, s2;
                if (dot >= 0.f) { s0 = P0.x; s1 = P1.x; s2 = P2.x; }
                else {
                    float sc = dot * invA;
                    s0 = P0.x - sc * D0.x; s1 = P1.x - sc * D1.x; s2 = P2.x - sc * D2.x;
                }
                sum[o][0] += 0.2f * P0.x + 0.8f * s0;
                sum[o][1] += 0.2f * P1.x + 0.8f * s1;
                sum[o][2] += 0.2f * P2.x + 0.8f * s2;
            }
            {
                float dot = P0.y * D0.y + P1.y * D1.y + P2.y * D2.y;
                float s0, s1, s2;
                if (dot >= 0.f) { s0 = P0.y; s1 = P1.y; s2 = P2.y; }
                else {
                    float sc = dot * invB;
                    s0 = P0.y - sc * D0.y; s1 = P1.y - sc * D1.y; s2 = P2.y - sc * D2.y;
                }
                sum[o][0] += 0.2f * P0.y + 0.8f * s0;
                sum[o][1] += 0.2f * P1.y + 0.8f * s1;
                sum[o][2] += 0.2f * P2.y + 0.8f * s2;
            }
        }
    }
    #pragma unroll
    for (int o = 0; o < OT; o++)
        #pragma unroll
        for (int dd = 0; dd < 3; dd++) {
            float v = sum[o][dd];
            #pragma unroll
            for (int s = 16; s; s >>= 1) v += __shfl_down_sync(0xffffffffu, v, s);
            if ((tid & 31) == 0) atomicAdd(&sacc[o * 3 + dd], v);
        }
    __syncthreads();
    if (tid < OT * 3) out[b * 1023 + o0 * 3 + tid] = sacc[tid] * (1.f / NPT);
}

// ================= launch =================
static constexpr size_t ymap_smem(int CIN, int COUT)
{
    return (size_t)(4 * CIN * COUT + 3 * CIN * 32) * 4;
}
static constexpr size_t knn_smem(int D)
{
    return (size_t)16 * NPT * 4 + (size_t)D * 8 * 8;
}

extern "C" void kernel_launch(void* const* d_in, const int* in_sizes, int n_in,
                              void* d_out, int out_size)
{
    const float* x   = (const float*)d_in[0];
    const float* Wf0 = (const float*)d_in[1];
    const float* Wd0 = (const float*)d_in[2];
    const float* Wf1 = (const float*)d_in[3];
    const float* Wd1 = (const float*)d_in[4];
    const float* Wf2 = (const float*)d_in[5];
    const float* Wd2 = (const float*)d_in[6];
    const float* Wf3 = (const float*)d_in[7];
    const float* Wd3 = (const float*)d_in[8];
    const float* Wf4 = (const float*)d_in[9];
    const float* Wd4 = (const float*)d_in[10];
    float* out = (float*)d_out;

    float* feat = nullptr;
    cudaGetSymbolAddress((void**)&feat, g_feat);

    static cudaStream_t s1;
    static cudaEvent_t evF, evJ;
    static bool init_done = false;
    if (!init_done) {
        cudaStreamCreateWithFlags(&s1, cudaStreamNonBlocking);
        cudaEventCreateWithFlags(&evF, cudaEventDisableTiming);
        cudaEventCreateWithFlags(&evJ, cudaEventDisableTiming);
        cudaFuncSetAttribute(ymap_kernel<42, 85>,
                             cudaFuncAttributeMaxDynamicSharedMemorySize,
                             (int)ymap_smem(42, 85));
        cudaFuncSetAttribute(knn_kernel<3>,
                             cudaFuncAttributeMaxDynamicSharedMemorySize,
                             (int)knn_smem(3));
        cudaFuncSetAttribute(knn_kernel<63>,
                             cudaFuncAttributeMaxDynamicSharedMemorySize,
                             (int)knn_smem(63));
        cudaFuncSetAttribute(knn_kernel<126>,
                             cudaFuncAttributeMaxDynamicSharedMemorySize,
                             (int)knn_smem(126));
        init_done = true;
    }

    const int KNNG = BATCH * (NPT / 16);     // 512
    const int YG   = TOTPT / 32;             // 256

    // ---- layer 0 : CIN=1, D=3, out=21 -> feat[0:21) ----
    cudaEventRecord(evF, 0);
    cudaStreamWaitEvent(s1, evF, 0);
    ymap_kernel<1, 21><<<YG, 256, ymap_smem(1, 21), s1>>>(x, 1, 0, Wf0, Wd0);
    cudaEventRecord(evJ, s1);
    knn_kernel<3><<<KNNG, 256, knn_smem(3)>>>(x, 1, 0);
    cudaStreamWaitEvent(0, evJ, 0);
    pair_kernel<21, 12, 256><<<(TOTPT + 11) / 12, 256>>>(0);

    // ---- layer 1 : CIN=21, D=63, out=21 -> feat[21:42) ----
    cudaEventRecord(evF, 0);
    cudaStreamWaitEvent(s1, evF, 0);
    ymap_kernel<21, 21><<<YG, 256, ymap_smem(21, 21), s1>>>(feat, CTOT, 0, Wf1, Wd1);
    cudaEventRecord(evJ, s1);
    knn_kernel<63><<<KNNG, 256, knn_smem(63)>>>(feat, CTOT, 0);
    cudaStreamWaitEvent(0, evJ, 0);
    pair_kernel<21, 12, 256><<<(TOTPT + 11) / 12, 256>>>(21);

    // ---- layer 2 : CIN=21, D=63, out=42 -> feat[42:84) ----
    cudaEventRecord(evF, 0);
    cudaStreamWaitEvent(s1, evF, 0);
    ymap_kernel<21, 42><<<YG, 256, ymap_smem(21, 42), s1>>>(feat, CTOT, 21, Wf2, Wd2);
    cudaEventRecord(evJ, s1);
    knn_kernel<63><<<KNNG, 256, knn_smem(63)>>>(feat, CTOT, 21);
    cudaStreamWaitEvent(0, evJ, 0);
    pair_kernel<42, 6, 256><<<(TOTPT + 5) / 6, 256>>>(42);

    // ---- layer 3 : CIN=42, D=126, out=85 -> feat[84:169) ----
    // side stream also computes final partial sums over c in [0,84)
    cudaEventRecord(evF, 0);
    cudaStreamWaitEvent(s1, evF, 0);
    ymap_kernel<42, 85><<<YG, 256, ymap_smem(42, 85), s1>>>(feat, CTOT, 42, Wf3, Wd3);
    final_part<<<BATCH * 31, 256, 0, s1>>>(Wf4, Wd4);
    cudaEventRecord(evJ, s1);
    knn_kernel<126><<<KNNG, 256, knn_smem(126)>>>(feat, CTOT, 42);
    cudaStreamWaitEvent(0, evJ, 0);
    pair_kernel<85, 3, 256><<<(TOTPT + 2) / 3, 256>>>(84);

    // ---- final VN layer remainder c in [84,169), leaky + mean over N ----
    final_rest<<<BATCH * 31, 256>>>(Wf4, Wd4, out);
}